// round 13
// baseline (speedup 1.0000x reference)
#include <cuda_runtime.h>
#include <cuda_bf16.h>
#include <cstdint>

#if defined(__CUDA_ARCH_FEAT_SM103_ALL) || defined(__CUDA_ARCH_FEAT_SM100_ALL) || \
    (defined(__CUDA_ARCH_SPECIFIC__) && (__CUDA_ARCH_SPECIFIC__ >= 1000))
#define HAS_TCGEN5 1
#else
#define HAS_TCGEN5 0
#endif

// ---------------- problem constants ----------------
#define NB   64
#define CIN  128
#define COUT 128
#define HH   56
#define WW   56
#define XN   (NB*CIN*HH*WW)
#define WN   (COUT*CIN*9)
#define WGROUPS (WN/16)            // 576

#define NPIXR   3712               // 58*64 padded pixel rows per image
#define GUARDR  64
#define GUARD_E (GUARDR*CIN)
#define NITEMS  448
#define NCTAS   444                // 3 full waves; CTAs 0..3 take a 2nd item

// ---------------- device scratch ----------------
__device__ __align__(256) __nv_bfloat16 g_x1[(size_t)(2*GUARDR + NB*NPIXR)*CIN];
__device__ __nv_bfloat16 g_wq9[9*COUT*CIN];   // [k=kh*3+kw][co][ci]

// ---------------- BFP quantization (exact, bf16-representable) ----------------
__device__ __forceinline__ void quant16(const float4* p, float* ov) {
    float v[16];
    float4 a = p[0], b = p[1], c = p[2], d = p[3];
    v[0]=a.x;v[1]=a.y;v[2]=a.z;v[3]=a.w; v[4]=b.x;v[5]=b.y;v[6]=b.z;v[7]=b.w;
    v[8]=c.x;v[9]=c.y;v[10]=c.z;v[11]=c.w; v[12]=d.x;v[13]=d.y;v[14]=d.z;v[15]=d.w;
    float m = 0.0f;
    #pragma unroll
    for (int i = 0; i < 16; i++) m = fmaxf(m, fabsf(v[i]));
    if (m > 0.0f) {
        int e = ((__float_as_int(m) >> 23) & 0xFF) - 127;
        float inv_s = ldexpf(1.0f, 7 - e);
        float s     = ldexpf(1.0f, e - 7);
        #pragma unroll
        for (int i = 0; i < 16; i++) {
            float q = rintf(v[i] * inv_s);
            q = fminf(127.0f, fmaxf(-127.0f, q));
            ov[i] = q * s;
        }
    } else {
        #pragma unroll
        for (int i = 0; i < 16; i++) ov[i] = 0.0f;
    }
}

// ---------------- fused prepass: quant x (+transpose/pad) AND quant w --------
// z = 0..63: image n (8 h-rows x 16 ci per (hc, cc) block).
// z = 64:    weight quantization (576 groups spread over (hc, cc) blocks).
__global__ __launch_bounds__(256)
void quant_pad_x(const float* __restrict__ in, const float* __restrict__ win) {
    const int hc = blockIdx.x, cc = blockIdx.y, nz = blockIdx.z;
    const int tid = threadIdx.x;

    if (nz == NB) {   // ---- weight path ----
        int g = (hc * 8 + cc) * 256 + tid;
        if (g < WGROUPS) {
            float ov[16];
            quant16(reinterpret_cast<const float4*>(win) + (size_t)g * 4, ov);
            #pragma unroll
            for (int i = 0; i < 16; i++) {
                int flat = g * 16 + i;
                int k  = flat % 9;
                int t2 = flat / 9;
                int ci = t2 % CIN;
                int co = t2 / CIN;
                g_wq9[(k * COUT + co) * CIN + ci] = __float2bfloat16(ov[i]);
            }
        }
        return;
    }

    __shared__ uint32_t sq[16][229];
    const int n = nz;
    const int h0 = hc * 8, ci0 = cc * 16;

    for (int g2 = tid; g2 < 448; g2 += 256) {
        int ci = g2 / 28, grp = g2 % 28;
        const float4* src = reinterpret_cast<const float4*>(
            in + ((size_t)(n * CIN + ci0 + ci) * (HH * WW) + h0 * WW + grp * 16));
        float ov[16];
        quant16(src, ov);
        int wb = grp * 8;
        #pragma unroll
        for (int j = 0; j < 8; j++) {
            uint32_t lo = __bfloat16_as_ushort(__float2bfloat16(ov[2*j]));
            uint32_t hi = __bfloat16_as_ushort(__float2bfloat16(ov[2*j+1]));
            sq[ci][wb + j] = (hi << 16) | lo;
        }
    }
    __syncthreads();

    __nv_bfloat16* img = g_x1 + GUARD_E + (size_t)n * NPIXR * CIN;
    const uint4 z4 = make_uint4(0, 0, 0, 0);

    // main pixels -> [pix][ci] via PRMT merges (1 op per bf16 pair)
    for (int i = tid; i < 896; i += 256) {
        int pos = i >> 1, half = i & 1;
        int r = pos / WW, w = pos % WW;
        int p56 = r * WW + w;
        int word = p56 >> 1;
        uint32_t sel = (p56 & 1) ? 0x7632u : 0x5410u;
        const int h8 = half * 8;
        uint4 v;
        v.x = __byte_perm(sq[h8+0][word], sq[h8+1][word], sel);
        v.y = __byte_perm(sq[h8+2][word], sq[h8+3][word], sel);
        v.z = __byte_perm(sq[h8+4][word], sq[h8+5][word], sel);
        v.w = __byte_perm(sq[h8+6][word], sq[h8+7][word], sel);
        int pix = (h0 + r + 1) * 64 + w;
        *reinterpret_cast<uint4*>(img + (size_t)pix * CIN + ci0 + half * 8) = v;
    }
    for (int i = tid; i < 128; i += 256) {
        int r = i >> 4, w2 = (i >> 1) & 7, half = i & 1;
        int pix = (h0 + r + 1) * 64 + 56 + w2;
        *reinterpret_cast<uint4*>(img + (size_t)pix * CIN + ci0 + half * 8) = z4;
    }
    if (hc == 0)
        for (int i = tid; i < 128; i += 256) {
            int pix = i >> 1, half = i & 1;
            *reinterpret_cast<uint4*>(img + (size_t)pix * CIN + ci0 + half * 8) = z4;
        }
    if (hc == 6)
        for (int i = tid; i < 128; i += 256) {
            int pix = 57 * 64 + (i >> 1), half = i & 1;
            *reinterpret_cast<uint4*>(img + (size_t)pix * CIN + ci0 + half * 8) = z4;
        }
    if (n == 0 && hc == 0 && cc == 0)
        for (int i = tid; i < GUARD_E / 8; i += 256)
            reinterpret_cast<uint4*>(g_x1)[i] = z4;
    if (n == NB-1 && hc == 6 && cc == 0) {
        uint4* back = reinterpret_cast<uint4*>(g_x1 + GUARD_E + (size_t)NB * NPIXR * CIN);
        for (int i = tid; i < GUARD_E / 8; i += 256) back[i] = z4;
    }
}

// ---------------- tcgen05 helpers ----------------
#if HAS_TCGEN5
__device__ __forceinline__ uint32_t elect_one_pred() {
    uint32_t pred;
    asm volatile("{\n\t.reg .pred p;\n\telect.sync _|p, 0xFFFFFFFF;\n\t"
                 "selp.b32 %0, 1, 0, p;\n\t}" : "=r"(pred));
    return pred;
}
#define TC_ALLOC(sm, n)  asm volatile("tcgen05.alloc.cta_group::1.sync.aligned.shared::cta.b32 [%0], %1;" :: "r"(sm), "r"((uint32_t)(n)) : "memory")
#define TC_DEALLOC(t, n) asm volatile("tcgen05.dealloc.cta_group::1.sync.aligned.b32 %0, %1;" :: "r"(t), "r"((uint32_t)(n)))
#define TC_RELINQ()      asm volatile("tcgen05.relinquish_alloc_permit.cta_group::1.sync.aligned;")
#define TC_COMMIT(mb)    asm volatile("tcgen05.commit.cta_group::1.mbarrier::arrive::one.shared::cluster.b64 [%0];" :: "r"(mb) : "memory")
#define TC_FENCE_AFTER() asm volatile("tcgen05.fence::after_thread_sync;" ::: "memory")
#define TC_WAIT_LD()     asm volatile("tcgen05.wait::ld.sync.aligned;" ::: "memory")
#define FENCE_ASYNC()    asm volatile("fence.proxy.async.shared::cta;" ::: "memory")
#define MBAR_INIT(mb, c) asm volatile("mbarrier.init.shared.b64 [%0], %1;" :: "r"(mb), "r"((uint32_t)(c)) : "memory")
#define CP_COMMIT()      asm volatile("cp.async.commit_group;" ::: "memory")
#define CP_WAIT0()       asm volatile("cp.async.wait_group 0;" ::: "memory")

__device__ __forceinline__ void cp16(uint32_t dst, const void* src) {
    asm volatile("cp.async.cg.shared.global [%0], [%1], 16;"
                 :: "r"(dst), "l"(src) : "memory");
}
__device__ __forceinline__ void mbar_wait(uint32_t mb, uint32_t parity) {
    asm volatile(
        "{\n\t.reg .pred P1;\n\t"
        "WL_%=:\n\t"
        "mbarrier.try_wait.parity.acquire.cta.shared::cta.b64 P1, [%0], %1, 0x989680;\n\t"
        "@P1 bra.uni WD_%=;\n\t"
        "bra.uni WL_%=;\n\t"
        "WD_%=:\n\t}"
        :: "r"(mb), "r"(parity) : "memory");
}
#define TC_LD_X32(r, ta) \
    asm volatile("tcgen05.ld.sync.aligned.32x32b.x32.b32 " \
        "{%0,%1,%2,%3,%4,%5,%6,%7,%8,%9,%10,%11,%12,%13,%14,%15," \
        "%16,%17,%18,%19,%20,%21,%22,%23,%24,%25,%26,%27,%28,%29,%30,%31}, [%32];" \
        : "=r"((r)[0]),"=r"((r)[1]),"=r"((r)[2]),"=r"((r)[3]),"=r"((r)[4]),"=r"((r)[5]),"=r"((r)[6]),"=r"((r)[7]), \
          "=r"((r)[8]),"=r"((r)[9]),"=r"((r)[10]),"=r"((r)[11]),"=r"((r)[12]),"=r"((r)[13]),"=r"((r)[14]),"=r"((r)[15]), \
          "=r"((r)[16]),"=r"((r)[17]),"=r"((r)[18]),"=r"((r)[19]),"=r"((r)[20]),"=r"((r)[21]),"=r"((r)[22]),"=r"((r)[23]), \
          "=r"((r)[24]),"=r"((r)[25]),"=r"((r)[26]),"=r"((r)[27]),"=r"((r)[28]),"=r"((r)[29]),"=r"((r)[30]),"=r"((r)[31]) \
        : "r"(ta))

__device__ __forceinline__ void mma_f16_ss(uint32_t d, uint64_t a, uint64_t b,
                                           uint32_t idesc, uint32_t en) {
    asm volatile(
        "{\n\t.reg .pred p;\n\tsetp.ne.u32 p, %4, 0;\n\t"
        "tcgen05.mma.cta_group::1.kind::f16 [%0], %1, %2, %3, {%5,%5,%5,%5}, p;\n\t}"
        :: "r"(d), "l"(a), "l"(b), "r"(idesc), "r"(en), "r"(0u) : "memory");
}
#endif // HAS_TCGEN5

__device__ __forceinline__ uint32_t smem_u32(const void* p) {
    uint32_t a;
    asm("{ .reg .u64 t; cvta.to.shared.u64 t, %1; cvt.u32.u64 %0, t; }" : "=r"(a) : "l"(p));
    return a;
}
__device__ __forceinline__ void stcs128(float* p, float4 v) {
    asm volatile("st.global.cs.v4.f32 [%0], {%1,%2,%3,%4};"
                 :: "l"(p), "f"(v.x), "f"(v.y), "f"(v.z), "f"(v.w) : "memory");
}
#define DESC_BASE ((2ULL<<61) | (1ULL<<46) | (64ULL<<32) | (1ULL<<16))
__device__ __forceinline__ uint64_t mk_desc(uint32_t a) {
    return DESC_BASE | (uint64_t)((a >> 4) & 0x3FFF);
}
// F32 acc, BF16 a/b, N=128, M=128
#define IDESC (0x10u | 0x80u | 0x400u | (16u<<17) | (8u<<24))

// ---------------- tcgen05 conv (R12 pipeline + batched epilogue loads) -------
#define SM_TPTR 0
#define SM_MBAR 16
#define SM_A0   1024
#define SM_A1   33792
#define SM_B    66560
#define NARB    80
#define CONV_SMEM (SM_B + 640*256)   // 230,400
#define MB_S(s)    (SM_MBAR + (s)*8)
#define MB_T(b,t)  (SM_MBAR + (9 + (b)*3 + (t))*8)
#define EPI_PITCH 132

__global__ __launch_bounds__(128, 1)
void conv_mma_kernel(float* __restrict__ out) {
#if HAS_TCGEN5
    extern __shared__ char smem[];
    const int tid = threadIdx.x;
    const int wid = tid >> 5, lane = tid & 31;
    const uint32_t sb = smem_u32(smem);

    auto stageA = [&](int s) {
        const int kw = s / 3, kh = s % 3;
        const char* gA = (const char*)(g_wq9 + (size_t)(kh * 3 + kw) * COUT * CIN);
        uint32_t abuf = sb + ((s & 1) ? SM_A1 : SM_A0);
        #pragma unroll
        for (int it = 0; it < 16; it++) {
            int i = tid + it * 128;
            int lr = i >> 4, c = i & 15;
            uint32_t byte = (uint32_t)((lr >> 3) + (c >> 3) * 16) * 1024u
                          + (uint32_t)(lr & 7) * 128u + (uint32_t)(c & 7) * 16u;
            byte ^= (byte >> 3) & 0x70u;
            cp16(abuf + byte, gA + ((size_t)lr << 8) + (c << 4));
        }
    };
    auto stageBchunk = [&](long long Q0, int kw, int c) {
        const char* gB = (const char*)(g_x1 + GUARD_E)
                       + (Q0 - 64 + (kw - 1) + 128 * c) * (CIN * 2);
        #pragma unroll
        for (int it = 0; it < 16; it++) {
            int i = tid + it * 128;
            int lr = i >> 4, c16 = i & 15;
            uint32_t byte = (uint32_t)((16 * c + (lr >> 3)) + (c16 >> 3) * NARB) * 1024u
                          + (uint32_t)(lr & 7) * 128u + (uint32_t)(c16 & 7) * 16u;
            byte ^= (byte >> 3) & 0x70u;
            cp16(sb + SM_B + byte, gB + ((size_t)lr << 8) + (c16 << 4));
        }
    };

    if (wid == 0) TC_ALLOC(sb + SM_TPTR, 512);
    if (tid == 0)
        for (int m = 0; m < 15; m++) MBAR_INIT(SM_MBAR + sb + m * 8, 1);
    __syncthreads();
    uint32_t tmem;
    asm volatile("ld.shared.b32 %0, [%1];" : "=r"(tmem) : "r"(sb + SM_TPTR));
    if (wid == 0) TC_RELINQ();

    const uint64_t adesc[2] = { mk_desc(sb + SM_A0), mk_desc(sb + SM_A1) };
    const uint64_t bdesc = mk_desc(sb + SM_B);

    for (int rep = 0, item = blockIdx.x; item < NITEMS; rep++, item += NCTAS) {
        const uint32_t par = (uint32_t)(rep & 1);
        const int n = item / 7, h0 = (item % 7) * 8;
        const long long Q0 = ((long long)n * 58 + h0 + 1) * 64;

        #pragma unroll
        for (int c = 0; c < 5; c++) stageBchunk(Q0, 0, c);
        stageA(0);
        CP_COMMIT(); CP_WAIT0(); FENCE_ASYNC();
        __syncthreads();

        for (int s = 0; s < 9; s++) {
            const int kh = s % 3;
            const bool boundary = (kh == 2) && (s < 8);
            if (tid < 32 && elect_one_pred()) {
                const uint64_t ad = adesc[s & 1];
                #pragma unroll
                for (int t = 0; t < 4; t++) {
                    const uint64_t bd = bdesc + (uint64_t)((16 * t + 8 * kh) * 64);
                    #pragma unroll
                    for (int k = 0; k < 8; k++)
                        mma_f16_ss(tmem + t * 128,
                                   ad + (uint64_t)((k & 3) * 2 + (k >> 2) * 1024),
                                   bd + (uint64_t)((k & 3) * 2 + (k >> 2) * 5120),
                                   IDESC, (s > 0 || k > 0) ? 1u : 0u);
                    if (boundary && t < 3) TC_COMMIT(sb + MB_T(s / 3, t));
                }
                TC_COMMIT(sb + MB_S(s));
            }
            if (s == 8) break;

            if (boundary) {
                const int kwn = s / 3 + 1;
                #pragma unroll
                for (int c = 0; c < 5; c++) {
                    if (c == 0)      mbar_wait(sb + MB_S(s - 1), par);
                    else if (c < 4)  mbar_wait(sb + MB_T(s / 3, c - 1), par);
                    else             mbar_wait(sb + MB_S(s), par);
                    if (c == 0) stageA(s + 1);
                    stageBchunk(Q0, kwn, c);
                    CP_COMMIT();
                }
            } else {
                if (s >= 1) mbar_wait(sb + MB_S(s - 1), par);
                stageA(s + 1);
                CP_COMMIT();
            }
            CP_WAIT0(); FENCE_ASYNC();
            __syncthreads();
        }

        mbar_wait(sb + MB_S(8), par);
        TC_FENCE_AFTER();
        __syncthreads();          // B smem dead: reuse for epilogue

        float* sepi = reinterpret_cast<float*>(smem + SM_B);
        float* ob = out + (size_t)n * COUT * (HH * WW);
        #pragma unroll
        for (int t = 0; t < 4; t++) {
            float* myrow = sepi + (wid * 32 + lane) * EPI_PITCH;
            #pragma unroll
            for (int chp = 0; chp < 2; chp++) {
                uint32_t v0[32], v1[32];
                TC_LD_X32(v0, tmem + t * 128 + (2 * chp) * 32);
                TC_LD_X32(v1, tmem + t * 128 + (2 * chp + 1) * 32);
                TC_WAIT_LD();
                #pragma unroll
                for (int j = 0; j < 32; j += 4)
                    *reinterpret_cast<float4*>(myrow + (2 * chp) * 32 + j) =
                        make_float4(__uint_as_float(v0[j]),   __uint_as_float(v0[j+1]),
                                    __uint_as_float(v0[j+2]), __uint_as_float(v0[j+3]));
                #pragma unroll
                for (int j = 0; j < 32; j += 4)
                    *reinterpret_cast<float4*>(myrow + (2 * chp + 1) * 32 + j) =
                        make_float4(__uint_as_float(v1[j]),   __uint_as_float(v1[j+1]),
                                    __uint_as_float(v1[j+2]), __uint_as_float(v1[j+3]));
            }
            __syncthreads();
            #pragma unroll
            for (int kq = 0; kq < 28; kq++) {
                int idx = kq * 128 + tid;
                int co = idx / 28, q = idx % 28;
                int w4 = q * 4;
                int r = w4 / 56, w = w4 % 56;
                float4 val = *reinterpret_cast<float4*>(sepi + co * EPI_PITCH + r * 64 + w);
                stcs128(ob + (size_t)co * (HH * WW) + (h0 + 2 * t + r) * WW + w, val);
            }
            __syncthreads();
        }
    }
    if (wid == 0) TC_DEALLOC(tmem, 512);
#endif // HAS_TCGEN5
}

// ---------------- launch ----------------
extern "C" void kernel_launch(void* const* d_in, const int* in_sizes, int n_in,
                              void* d_out, int out_size) {
    const float* x = (const float*)d_in[0];
    const float* w = (const float*)d_in[1];
    if (in_sizes[0] == WN && in_sizes[1] == XN) {
        x = (const float*)d_in[1];
        w = (const float*)d_in[0];
    }
    float* out = (float*)d_out;

    cudaFuncSetAttribute(conv_mma_kernel,
                         cudaFuncAttributeMaxDynamicSharedMemorySize, CONV_SMEM);

    quant_pad_x<<<dim3(7, 8, NB + 1), 256>>>(x, w);
    conv_mma_kernel<<<NCTAS, 128, CONV_SMEM>>>(out);
}

// round 14
// speedup vs baseline: 1.0466x; 1.0466x over previous
#include <cuda_runtime.h>
#include <cuda_bf16.h>
#include <cstdint>

#if defined(__CUDA_ARCH_FEAT_SM103_ALL) || defined(__CUDA_ARCH_FEAT_SM100_ALL) || \
    (defined(__CUDA_ARCH_SPECIFIC__) && (__CUDA_ARCH_SPECIFIC__ >= 1000))
#define HAS_TCGEN5 1
#else
#define HAS_TCGEN5 0
#endif

// ---------------- problem constants ----------------
#define NB   64
#define CIN  128
#define COUT 128
#define HH   56
#define WW   56
#define XN   (NB*CIN*HH*WW)
#define WN   (COUT*CIN*9)
#define WGROUPS (WN/16)            // 576

#define NPIXR   3712               // 58*64 padded pixel rows per image
#define GUARDR  64
#define GUARD_E (GUARDR*CIN)
#define NITEMS  448
#define NCTAS   444                // 3 full waves; CTAs 0..3 take a 2nd item

// ---------------- device scratch ----------------
__device__ __align__(256) __nv_bfloat16 g_x1[(size_t)(2*GUARDR + NB*NPIXR)*CIN];
__device__ __nv_bfloat16 g_wq9[9*COUT*CIN];   // [k=kh*3+kw][co][ci]

// ---------------- BFP quantization (exact, bf16-representable) ----------------
__device__ __forceinline__ void quant16(const float4* p, float* ov) {
    float v[16];
    float4 a = p[0], b = p[1], c = p[2], d = p[3];
    v[0]=a.x;v[1]=a.y;v[2]=a.z;v[3]=a.w; v[4]=b.x;v[5]=b.y;v[6]=b.z;v[7]=b.w;
    v[8]=c.x;v[9]=c.y;v[10]=c.z;v[11]=c.w; v[12]=d.x;v[13]=d.y;v[14]=d.z;v[15]=d.w;
    float m = 0.0f;
    #pragma unroll
    for (int i = 0; i < 16; i++) m = fmaxf(m, fabsf(v[i]));
    if (m > 0.0f) {
        int e = ((__float_as_int(m) >> 23) & 0xFF) - 127;
        float inv_s = ldexpf(1.0f, 7 - e);
        float s     = ldexpf(1.0f, e - 7);
        #pragma unroll
        for (int i = 0; i < 16; i++) {
            float q = rintf(v[i] * inv_s);
            q = fminf(127.0f, fmaxf(-127.0f, q));
            ov[i] = q * s;
        }
    } else {
        #pragma unroll
        for (int i = 0; i < 16; i++) ov[i] = 0.0f;
    }
}

// ---------------- fused prepass: quant x (+transpose/pad) AND quant w --------
__global__ __launch_bounds__(256)
void quant_pad_x(const float* __restrict__ in, const float* __restrict__ win) {
    const int hc = blockIdx.x, cc = blockIdx.y, nz = blockIdx.z;
    const int tid = threadIdx.x;

    if (nz == NB) {   // ---- weight path ----
        int g = (hc * 8 + cc) * 256 + tid;
        if (g < WGROUPS) {
            float ov[16];
            quant16(reinterpret_cast<const float4*>(win) + (size_t)g * 4, ov);
            #pragma unroll
            for (int i = 0; i < 16; i++) {
                int flat = g * 16 + i;
                int k  = flat % 9;
                int t2 = flat / 9;
                int ci = t2 % CIN;
                int co = t2 / CIN;
                g_wq9[(k * COUT + co) * CIN + ci] = __float2bfloat16(ov[i]);
            }
        }
        return;
    }

    __shared__ uint32_t sq[16][229];
    const int n = nz;
    const int h0 = hc * 8, ci0 = cc * 16;

    for (int g2 = tid; g2 < 448; g2 += 256) {
        int ci = g2 / 28, grp = g2 % 28;
        const float4* src = reinterpret_cast<const float4*>(
            in + ((size_t)(n * CIN + ci0 + ci) * (HH * WW) + h0 * WW + grp * 16));
        float ov[16];
        quant16(src, ov);
        int wb = grp * 8;
        #pragma unroll
        for (int j = 0; j < 8; j++) {
            uint32_t lo = __bfloat16_as_ushort(__float2bfloat16(ov[2*j]));
            uint32_t hi = __bfloat16_as_ushort(__float2bfloat16(ov[2*j+1]));
            sq[ci][wb + j] = (hi << 16) | lo;
        }
    }
    __syncthreads();

    __nv_bfloat16* img = g_x1 + GUARD_E + (size_t)n * NPIXR * CIN;
    const uint4 z4 = make_uint4(0, 0, 0, 0);

    for (int i = tid; i < 896; i += 256) {
        int pos = i >> 1, half = i & 1;
        int r = pos / WW, w = pos % WW;
        int p56 = r * WW + w;
        int word = p56 >> 1;
        uint32_t sel = (p56 & 1) ? 0x7632u : 0x5410u;
        const int h8 = half * 8;
        uint4 v;
        v.x = __byte_perm(sq[h8+0][word], sq[h8+1][word], sel);
        v.y = __byte_perm(sq[h8+2][word], sq[h8+3][word], sel);
        v.z = __byte_perm(sq[h8+4][word], sq[h8+5][word], sel);
        v.w = __byte_perm(sq[h8+6][word], sq[h8+7][word], sel);
        int pix = (h0 + r + 1) * 64 + w;
        *reinterpret_cast<uint4*>(img + (size_t)pix * CIN + ci0 + half * 8) = v;
    }
    for (int i = tid; i < 128; i += 256) {
        int r = i >> 4, w2 = (i >> 1) & 7, half = i & 1;
        int pix = (h0 + r + 1) * 64 + 56 + w2;
        *reinterpret_cast<uint4*>(img + (size_t)pix * CIN + ci0 + half * 8) = z4;
    }
    if (hc == 0)
        for (int i = tid; i < 128; i += 256) {
            int pix = i >> 1, half = i & 1;
            *reinterpret_cast<uint4*>(img + (size_t)pix * CIN + ci0 + half * 8) = z4;
        }
    if (hc == 6)
        for (int i = tid; i < 128; i += 256) {
            int pix = 57 * 64 + (i >> 1), half = i & 1;
            *reinterpret_cast<uint4*>(img + (size_t)pix * CIN + ci0 + half * 8) = z4;
        }
    if (n == 0 && hc == 0 && cc == 0)
        for (int i = tid; i < GUARD_E / 8; i += 256)
            reinterpret_cast<uint4*>(g_x1)[i] = z4;
    if (n == NB-1 && hc == 6 && cc == 0) {
        uint4* back = reinterpret_cast<uint4*>(g_x1 + GUARD_E + (size_t)NB * NPIXR * CIN);
        for (int i = tid; i < GUARD_E / 8; i += 256) back[i] = z4;
    }
}

// ---------------- tcgen05 helpers ----------------
#if HAS_TCGEN5
__device__ __forceinline__ uint32_t elect_one_pred() {
    uint32_t pred;
    asm volatile("{\n\t.reg .pred p;\n\telect.sync _|p, 0xFFFFFFFF;\n\t"
                 "selp.b32 %0, 1, 0, p;\n\t}" : "=r"(pred));
    return pred;
}
#define TC_ALLOC(sm, n)  asm volatile("tcgen05.alloc.cta_group::1.sync.aligned.shared::cta.b32 [%0], %1;" :: "r"(sm), "r"((uint32_t)(n)) : "memory")
#define TC_DEALLOC(t, n) asm volatile("tcgen05.dealloc.cta_group::1.sync.aligned.b32 %0, %1;" :: "r"(t), "r"((uint32_t)(n)))
#define TC_RELINQ()      asm volatile("tcgen05.relinquish_alloc_permit.cta_group::1.sync.aligned;")
#define TC_COMMIT(mb)    asm volatile("tcgen05.commit.cta_group::1.mbarrier::arrive::one.shared::cluster.b64 [%0];" :: "r"(mb) : "memory")
#define TC_FENCE_AFTER() asm volatile("tcgen05.fence::after_thread_sync;" ::: "memory")
#define TC_WAIT_LD()     asm volatile("tcgen05.wait::ld.sync.aligned;" ::: "memory")
#define FENCE_ASYNC()    asm volatile("fence.proxy.async.shared::cta;" ::: "memory")
#define MBAR_INIT(mb, c) asm volatile("mbarrier.init.shared.b64 [%0], %1;" :: "r"(mb), "r"((uint32_t)(c)) : "memory")
#define CP_COMMIT()      asm volatile("cp.async.commit_group;" ::: "memory")
#define CP_WAIT0()       asm volatile("cp.async.wait_group 0;" ::: "memory")

__device__ __forceinline__ void cp16(uint32_t dst, const void* src) {
    asm volatile("cp.async.cg.shared.global [%0], [%1], 16;"
                 :: "r"(dst), "l"(src) : "memory");
}
__device__ __forceinline__ void mbar_wait(uint32_t mb, uint32_t parity) {
    asm volatile(
        "{\n\t.reg .pred P1;\n\t"
        "WL_%=:\n\t"
        "mbarrier.try_wait.parity.acquire.cta.shared::cta.b64 P1, [%0], %1, 0x989680;\n\t"
        "@P1 bra.uni WD_%=;\n\t"
        "bra.uni WL_%=;\n\t"
        "WD_%=:\n\t}"
        :: "r"(mb), "r"(parity) : "memory");
}
#define TC_LD_X32(r, ta) \
    asm volatile("tcgen05.ld.sync.aligned.32x32b.x32.b32 " \
        "{%0,%1,%2,%3,%4,%5,%6,%7,%8,%9,%10,%11,%12,%13,%14,%15," \
        "%16,%17,%18,%19,%20,%21,%22,%23,%24,%25,%26,%27,%28,%29,%30,%31}, [%32];" \
        : "=r"((r)[0]),"=r"((r)[1]),"=r"((r)[2]),"=r"((r)[3]),"=r"((r)[4]),"=r"((r)[5]),"=r"((r)[6]),"=r"((r)[7]), \
          "=r"((r)[8]),"=r"((r)[9]),"=r"((r)[10]),"=r"((r)[11]),"=r"((r)[12]),"=r"((r)[13]),"=r"((r)[14]),"=r"((r)[15]), \
          "=r"((r)[16]),"=r"((r)[17]),"=r"((r)[18]),"=r"((r)[19]),"=r"((r)[20]),"=r"((r)[21]),"=r"((r)[22]),"=r"((r)[23]), \
          "=r"((r)[24]),"=r"((r)[25]),"=r"((r)[26]),"=r"((r)[27]),"=r"((r)[28]),"=r"((r)[29]),"=r"((r)[30]),"=r"((r)[31]) \
        : "r"(ta))

__device__ __forceinline__ void mma_f16_ss(uint32_t d, uint64_t a, uint64_t b,
                                           uint32_t idesc, uint32_t en) {
    asm volatile(
        "{\n\t.reg .pred p;\n\tsetp.ne.u32 p, %4, 0;\n\t"
        "tcgen05.mma.cta_group::1.kind::f16 [%0], %1, %2, %3, {%5,%5,%5,%5}, p;\n\t}"
        :: "r"(d), "l"(a), "l"(b), "r"(idesc), "r"(en), "r"(0u) : "memory");
}
#endif // HAS_TCGEN5

__device__ __forceinline__ uint32_t smem_u32(const void* p) {
    uint32_t a;
    asm("{ .reg .u64 t; cvta.to.shared.u64 t, %1; cvt.u32.u64 %0, t; }" : "=r"(a) : "l"(p));
    return a;
}
__device__ __forceinline__ void stcs128(float* p, float4 v) {
    asm volatile("st.global.cs.v4.f32 [%0], {%1,%2,%3,%4};"
                 :: "l"(p), "f"(v.x), "f"(v.y), "f"(v.z), "f"(v.w) : "memory");
}
#define DESC_BASE ((2ULL<<61) | (1ULL<<46) | (64ULL<<32) | (1ULL<<16))
__device__ __forceinline__ uint64_t mk_desc(uint32_t a) {
    return DESC_BASE | (uint64_t)((a >> 4) & 0x3FFF);
}
// F32 acc, BF16 a/b, N=256, M=128
#define IDESC (0x10u | 0x80u | 0x400u | (32u<<17) | (8u<<24))

// ---------------- tcgen05 conv: N=256 dispatches (SMEM-BW relief) ------------
// CTA item = (n, 8 out rows). D = 2 tiles of N=256 (4 out rows each) in TMEM
// cols 256t. Window row offset for (t, kh) = 256t + 64kh (8-aligned). Boundary
// restage gated on tile-0 commit + stage commits.
#define SM_TPTR 0
#define SM_MBAR 16
#define SM_A0   1024
#define SM_A1   33792
#define SM_B    66560
#define NARB    80
#define CONV_SMEM (SM_B + 640*256)   // 230,400
#define MB_S(s)    (SM_MBAR + (s)*8)
#define MB_T(b)    (SM_MBAR + (9 + (b))*8)   // boundary tile-0 commits (b=0,1)
#define EPI_PITCH 68

__global__ __launch_bounds__(128, 1)
void conv_mma_kernel(float* __restrict__ out) {
#if HAS_TCGEN5
    extern __shared__ char smem[];
    const int tid = threadIdx.x;
    const int wid = tid >> 5, lane = tid & 31;
    const uint32_t sb = smem_u32(smem);

    auto stageA = [&](int s) {
        const int kw = s / 3, kh = s % 3;
        const char* gA = (const char*)(g_wq9 + (size_t)(kh * 3 + kw) * COUT * CIN);
        uint32_t abuf = sb + ((s & 1) ? SM_A1 : SM_A0);
        #pragma unroll
        for (int it = 0; it < 16; it++) {
            int i = tid + it * 128;
            int lr = i >> 4, c = i & 15;
            uint32_t byte = (uint32_t)((lr >> 3) + (c >> 3) * 16) * 1024u
                          + (uint32_t)(lr & 7) * 128u + (uint32_t)(c & 7) * 16u;
            byte ^= (byte >> 3) & 0x70u;
            cp16(abuf + byte, gA + ((size_t)lr << 8) + (c << 4));
        }
    };
    auto stageBchunk = [&](long long Q0, int kw, int c) {
        const char* gB = (const char*)(g_x1 + GUARD_E)
                       + (Q0 - 64 + (kw - 1) + 128 * c) * (CIN * 2);
        #pragma unroll
        for (int it = 0; it < 16; it++) {
            int i = tid + it * 128;
            int lr = i >> 4, c16 = i & 15;
            uint32_t byte = (uint32_t)((16 * c + (lr >> 3)) + (c16 >> 3) * NARB) * 1024u
                          + (uint32_t)(lr & 7) * 128u + (uint32_t)(c16 & 7) * 16u;
            byte ^= (byte >> 3) & 0x70u;
            cp16(sb + SM_B + byte, gB + ((size_t)lr << 8) + (c16 << 4));
        }
    };

    if (wid == 0) TC_ALLOC(sb + SM_TPTR, 512);
    if (tid == 0)
        for (int m = 0; m < 11; m++) MBAR_INIT(SM_MBAR + sb + m * 8, 1);
    __syncthreads();
    uint32_t tmem;
    asm volatile("ld.shared.b32 %0, [%1];" : "=r"(tmem) : "r"(sb + SM_TPTR));
    if (wid == 0) TC_RELINQ();

    const uint64_t adesc[2] = { mk_desc(sb + SM_A0), mk_desc(sb + SM_A1) };
    const uint64_t bdesc = mk_desc(sb + SM_B);

    for (int rep = 0, item = blockIdx.x; item < NITEMS; rep++, item += NCTAS) {
        const uint32_t par = (uint32_t)(rep & 1);
        const int n = item / 7, h0 = (item % 7) * 8;
        const long long Q0 = ((long long)n * 58 + h0 + 1) * 64;

        #pragma unroll
        for (int c = 0; c < 5; c++) stageBchunk(Q0, 0, c);
        stageA(0);
        CP_COMMIT(); CP_WAIT0(); FENCE_ASYNC();
        __syncthreads();

        for (int s = 0; s < 9; s++) {
            const int kh = s % 3;
            const bool boundary = (kh == 2) && (s < 8);
            if (tid < 32 && elect_one_pred()) {
                const uint64_t ad = adesc[s & 1];
                #pragma unroll
                for (int t = 0; t < 2; t++) {
                    const uint64_t bd = bdesc + (uint64_t)((32 * t + 8 * kh) * 64);
                    #pragma unroll
                    for (int k = 0; k < 8; k++)
                        mma_f16_ss(tmem + t * 256,
                                   ad + (uint64_t)((k & 3) * 2 + (k >> 2) * 1024),
                                   bd + (uint64_t)((k & 3) * 2 + (k >> 2) * 5120),
                                   IDESC, (s > 0 || k > 0) ? 1u : 0u);
                    if (boundary && t == 0) TC_COMMIT(sb + MB_T(s / 3));
                }
                TC_COMMIT(sb + MB_S(s));
            }
            if (s == 8) break;

            if (boundary) {
                const int kwn = s / 3 + 1;
                #pragma unroll
                for (int c = 0; c < 5; c++) {
                    if (c == 0)      mbar_wait(sb + MB_S(s - 1), par);  // chunk0: only kh<2 read it
                    else if (c == 1) mbar_wait(sb + MB_T(s / 3), par);  // chunks1-2: tile0 done
                    else if (c == 3) mbar_wait(sb + MB_S(s), par);      // chunks3-4: tile1 done
                    if (c == 0) stageA(s + 1);
                    stageBchunk(Q0, kwn, c);
                    CP_COMMIT();
                }
            } else {
                if (s >= 1) mbar_wait(sb + MB_S(s - 1), par);
                stageA(s + 1);
                CP_COMMIT();
            }
            CP_WAIT0(); FENCE_ASYNC();
            __syncthreads();
        }

        mbar_wait(sb + MB_S(8), par);
        TC_FENCE_AFTER();
        __syncthreads();          // B smem dead: reuse for epilogue

        // ---- epilogue: per (tile, row) pass: 128 co x 64 cols ----
        float* sepi = reinterpret_cast<float*>(smem + SM_B);
        float* ob = out + (size_t)n * COUT * (HH * WW);
        const int co = wid * 32 + lane;
        #pragma unroll
        for (int t = 0; t < 2; t++) {
            #pragma unroll
            for (int r = 0; r < 4; r++) {
                uint32_t v0[32], v1[32];
                TC_LD_X32(v0, tmem + t * 256 + r * 64);
                TC_LD_X32(v1, tmem + t * 256 + r * 64 + 32);
                TC_WAIT_LD();
                float* myrow = sepi + co * EPI_PITCH;
                #pragma unroll
                for (int j = 0; j < 32; j += 4)
                    *reinterpret_cast<float4*>(myrow + j) =
                        make_float4(__uint_as_float(v0[j]),   __uint_as_float(v0[j+1]),
                                    __uint_as_float(v0[j+2]), __uint_as_float(v0[j+3]));
                #pragma unroll
                for (int j = 0; j < 24; j += 4)   // cols 32..55 only
                    *reinterpret_cast<float4*>(myrow + 32 + j) =
                        make_float4(__uint_as_float(v1[j]),   __uint_as_float(v1[j+1]),
                                    __uint_as_float(v1[j+2]), __uint_as_float(v1[j+3]));
                __syncthreads();
                #pragma unroll
                for (int kq = 0; kq < 14; kq++) {
                    int idx = kq * 128 + tid;
                    int co2 = idx / 14, q = idx % 14;
                    int w = q * 4;
                    float4 val = *reinterpret_cast<float4*>(sepi + co2 * EPI_PITCH + w);
                    stcs128(ob + (size_t)co2 * (HH * WW) + (h0 + 4 * t + r) * WW + w, val);
                }
                __syncthreads();
            }
        }
    }
    if (wid == 0) TC_DEALLOC(tmem, 512);
#endif // HAS_TCGEN5
}

// ---------------- launch ----------------
extern "C" void kernel_launch(void* const* d_in, const int* in_sizes, int n_in,
                              void* d_out, int out_size) {
    const float* x = (const float*)d_in[0];
    const float* w = (const float*)d_in[1];
    if (in_sizes[0] == WN && in_sizes[1] == XN) {
        x = (const float*)d_in[1];
        w = (const float*)d_in[0];
    }
    float* out = (float*)d_out;

    cudaFuncSetAttribute(conv_mma_kernel,
                         cudaFuncAttributeMaxDynamicSharedMemorySize, CONV_SMEM);

    quant_pad_x<<<dim3(7, 8, NB + 1), 256>>>(x, w);
    conv_mma_kernel<<<NCTAS, 128, CONV_SMEM>>>(out);
}

// round 16
// speedup vs baseline: 1.0695x; 1.0219x over previous
#include <cuda_runtime.h>
#include <cuda_bf16.h>
#include <cstdint>

#if defined(__CUDA_ARCH_FEAT_SM103_ALL) || defined(__CUDA_ARCH_FEAT_SM100_ALL) || \
    (defined(__CUDA_ARCH_SPECIFIC__) && (__CUDA_ARCH_SPECIFIC__ >= 1000))
#define HAS_TCGEN5 1
#else
#define HAS_TCGEN5 0
#endif

// ---------------- problem constants ----------------
#define NB   64
#define CIN  128
#define COUT 128
#define HH   56
#define WW   56
#define XN   (NB*CIN*HH*WW)
#define WN   (COUT*CIN*9)
#define WGROUPS (WN/16)            // 576

#define NPIXR   3712               // 58*64 padded pixel rows per image
#define GUARDR  64
#define GUARD_E (GUARDR*CIN)
#define NITEMS  448                // 64 images x 7 groups of 8 out rows
#define NCTAS   444

// ---------------- device scratch ----------------
__device__ __align__(256) __nv_bfloat16 g_x1[(size_t)(2*GUARDR + NB*NPIXR)*CIN];
__device__ __nv_bfloat16 g_wq9[9*COUT*CIN];   // [k=kh*3+kw][co][ci]

// ---------------- BFP quantization (exact, bf16-representable) ----------------
__device__ __forceinline__ void quant16(const float4* p, float* ov) {
    float v[16];
    float4 a = p[0], b = p[1], c = p[2], d = p[3];
    v[0]=a.x;v[1]=a.y;v[2]=a.z;v[3]=a.w; v[4]=b.x;v[5]=b.y;v[6]=b.z;v[7]=b.w;
    v[8]=c.x;v[9]=c.y;v[10]=c.z;v[11]=c.w; v[12]=d.x;v[13]=d.y;v[14]=d.z;v[15]=d.w;
    float m = 0.0f;
    #pragma unroll
    for (int i = 0; i < 16; i++) m = fmaxf(m, fabsf(v[i]));
    if (m > 0.0f) {
        int e = ((__float_as_int(m) >> 23) & 0xFF) - 127;
        float inv_s = ldexpf(1.0f, 7 - e);
        float s     = ldexpf(1.0f, e - 7);
        #pragma unroll
        for (int i = 0; i < 16; i++) {
            float q = rintf(v[i] * inv_s);
            q = fminf(127.0f, fmaxf(-127.0f, q));
            ov[i] = q * s;
        }
    } else {
        #pragma unroll
        for (int i = 0; i < 16; i++) ov[i] = 0.0f;
    }
}

// ---------------- fused prepass: quant x (+transpose/pad) AND quant w --------
__global__ __launch_bounds__(256)
void quant_pad_x(const float* __restrict__ in, const float* __restrict__ win) {
    const int hc = blockIdx.x, cc = blockIdx.y, nz = blockIdx.z;
    const int tid = threadIdx.x;

    if (nz == NB) {   // ---- weight path ----
        int g = (hc * 8 + cc) * 256 + tid;
        if (g < WGROUPS) {
            float ov[16];
            quant16(reinterpret_cast<const float4*>(win) + (size_t)g * 4, ov);
            #pragma unroll
            for (int i = 0; i < 16; i++) {
                int flat = g * 16 + i;
                int k  = flat % 9;
                int t2 = flat / 9;
                int ci = t2 % CIN;
                int co = t2 / CIN;
                g_wq9[(k * COUT + co) * CIN + ci] = __float2bfloat16(ov[i]);
            }
        }
        return;
    }

    __shared__ uint32_t sq[16][229];
    const int n = nz;
    const int h0 = hc * 8, ci0 = cc * 16;

    for (int g2 = tid; g2 < 448; g2 += 256) {
        int ci = g2 / 28, grp = g2 % 28;
        const float4* src = reinterpret_cast<const float4*>(
            in + ((size_t)(n * CIN + ci0 + ci) * (HH * WW) + h0 * WW + grp * 16));
        float ov[16];
        quant16(src, ov);
        int wb = grp * 8;
        #pragma unroll
        for (int j = 0; j < 8; j++) {
            uint32_t lo = __bfloat16_as_ushort(__float2bfloat16(ov[2*j]));
            uint32_t hi = __bfloat16_as_ushort(__float2bfloat16(ov[2*j+1]));
            sq[ci][wb + j] = (hi << 16) | lo;
        }
    }
    __syncthreads();

    __nv_bfloat16* img = g_x1 + GUARD_E + (size_t)n * NPIXR * CIN;
    const uint4 z4 = make_uint4(0, 0, 0, 0);

    for (int i = tid; i < 896; i += 256) {
        int pos = i >> 1, half = i & 1;
        int r = pos / WW, w = pos % WW;
        int p56 = r * WW + w;
        int word = p56 >> 1;
        uint32_t sel = (p56 & 1) ? 0x7632u : 0x5410u;
        const int h8 = half * 8;
        uint4 v;
        v.x = __byte_perm(sq[h8+0][word], sq[h8+1][word], sel);
        v.y = __byte_perm(sq[h8+2][word], sq[h8+3][word], sel);
        v.z = __byte_perm(sq[h8+4][word], sq[h8+5][word], sel);
        v.w = __byte_perm(sq[h8+6][word], sq[h8+7][word], sel);
        int pix = (h0 + r + 1) * 64 + w;
        *reinterpret_cast<uint4*>(img + (size_t)pix * CIN + ci0 + half * 8) = v;
    }
    for (int i = tid; i < 128; i += 256) {
        int r = i >> 4, w2 = (i >> 1) & 7, half = i & 1;
        int pix = (h0 + r + 1) * 64 + 56 + w2;
        *reinterpret_cast<uint4*>(img + (size_t)pix * CIN + ci0 + half * 8) = z4;
    }
    if (hc == 0)
        for (int i = tid; i < 128; i += 256) {
            int pix = i >> 1, half = i & 1;
            *reinterpret_cast<uint4*>(img + (size_t)pix * CIN + ci0 + half * 8) = z4;
        }
    if (hc == 6)
        for (int i = tid; i < 128; i += 256) {
            int pix = 57 * 64 + (i >> 1), half = i & 1;
            *reinterpret_cast<uint4*>(img + (size_t)pix * CIN + ci0 + half * 8) = z4;
        }
    if (n == 0 && hc == 0 && cc == 0)
        for (int i = tid; i < GUARD_E / 8; i += 256)
            reinterpret_cast<uint4*>(g_x1)[i] = z4;
    if (n == NB-1 && hc == 6 && cc == 0) {
        uint4* back = reinterpret_cast<uint4*>(g_x1 + GUARD_E + (size_t)NB * NPIXR * CIN);
        for (int i = tid; i < GUARD_E / 8; i += 256) back[i] = z4;
    }
}

// ---------------- tcgen05 helpers ----------------
#if HAS_TCGEN5
__device__ __forceinline__ uint32_t elect_one_pred() {
    uint32_t pred;
    asm volatile("{\n\t.reg .pred p;\n\telect.sync _|p, 0xFFFFFFFF;\n\t"
                 "selp.b32 %0, 1, 0, p;\n\t}" : "=r"(pred));
    return pred;
}
#define TC_ALLOC(sm, n)  asm volatile("tcgen05.alloc.cta_group::1.sync.aligned.shared::cta.b32 [%0], %1;" :: "r"(sm), "r"((uint32_t)(n)) : "memory")
#define TC_DEALLOC(t, n) asm volatile("tcgen05.dealloc.cta_group::1.sync.aligned.b32 %0, %1;" :: "r"(t), "r"((uint32_t)(n)))
#define TC_RELINQ()      asm volatile("tcgen05.relinquish_alloc_permit.cta_group::1.sync.aligned;")
#define TC_COMMIT(mb)    asm volatile("tcgen05.commit.cta_group::1.mbarrier::arrive::one.shared::cluster.b64 [%0];" :: "r"(mb) : "memory")
#define TC_FENCE_AFTER() asm volatile("tcgen05.fence::after_thread_sync;" ::: "memory")
#define TC_WAIT_LD()     asm volatile("tcgen05.wait::ld.sync.aligned;" ::: "memory")
#define FENCE_ASYNC()    asm volatile("fence.proxy.async.shared::cta;" ::: "memory")
#define MBAR_INIT(mb, c) asm volatile("mbarrier.init.shared.b64 [%0], %1;" :: "r"(mb), "r"((uint32_t)(c)) : "memory")
#define CP_COMMIT()      asm volatile("cp.async.commit_group;" ::: "memory")
#define CP_WAIT0()       asm volatile("cp.async.wait_group 0;" ::: "memory")

__device__ __forceinline__ void cp16(uint32_t dst, const void* src) {
    asm volatile("cp.async.cg.shared.global [%0], [%1], 16;"
                 :: "r"(dst), "l"(src) : "memory");
}
__device__ __forceinline__ void mbar_wait(uint32_t mb, uint32_t parity) {
    asm volatile(
        "{\n\t.reg .pred P1;\n\t"
        "WL_%=:\n\t"
        "mbarrier.try_wait.parity.acquire.cta.shared::cta.b64 P1, [%0], %1, 0x989680;\n\t"
        "@P1 bra.uni WD_%=;\n\t"
        "bra.uni WL_%=;\n\t"
        "WD_%=:\n\t}"
        :: "r"(mb), "r"(parity) : "memory");
}
#define TC_LD_X32(r, ta) \
    asm volatile("tcgen05.ld.sync.aligned.32x32b.x32.b32 " \
        "{%0,%1,%2,%3,%4,%5,%6,%7,%8,%9,%10,%11,%12,%13,%14,%15," \
        "%16,%17,%18,%19,%20,%21,%22,%23,%24,%25,%26,%27,%28,%29,%30,%31}, [%32];" \
        : "=r"((r)[0]),"=r"((r)[1]),"=r"((r)[2]),"=r"((r)[3]),"=r"((r)[4]),"=r"((r)[5]),"=r"((r)[6]),"=r"((r)[7]), \
          "=r"((r)[8]),"=r"((r)[9]),"=r"((r)[10]),"=r"((r)[11]),"=r"((r)[12]),"=r"((r)[13]),"=r"((r)[14]),"=r"((r)[15]), \
          "=r"((r)[16]),"=r"((r)[17]),"=r"((r)[18]),"=r"((r)[19]),"=r"((r)[20]),"=r"((r)[21]),"=r"((r)[22]),"=r"((r)[23]), \
          "=r"((r)[24]),"=r"((r)[25]),"=r"((r)[26]),"=r"((r)[27]),"=r"((r)[28]),"=r"((r)[29]),"=r"((r)[30]),"=r"((r)[31]) \
        : "r"(ta))

__device__ __forceinline__ void mma_f16_ss(uint32_t d, uint64_t a, uint64_t b,
                                           uint32_t idesc, uint32_t en) {
    asm volatile(
        "{\n\t.reg .pred p;\n\tsetp.ne.u32 p, %4, 0;\n\t"
        "tcgen05.mma.cta_group::1.kind::f16 [%0], %1, %2, %3, {%5,%5,%5,%5}, p;\n\t}"
        :: "r"(d), "l"(a), "l"(b), "r"(idesc), "r"(en), "r"(0u) : "memory");
}
#endif // HAS_TCGEN5

__device__ __forceinline__ uint32_t smem_u32(const void* p) {
    uint32_t a;
    asm("{ .reg .u64 t; cvta.to.shared.u64 t, %1; cvt.u32.u64 %0, t; }" : "=r"(a) : "l"(p));
    return a;
}
__device__ __forceinline__ void stcs128(float* p, float4 v) {
    asm volatile("st.global.cs.v4.f32 [%0], {%1,%2,%3,%4};"
                 :: "l"(p), "f"(v.x), "f"(v.y), "f"(v.z), "f"(v.w) : "memory");
}
#define DESC_BASE ((2ULL<<61) | (1ULL<<46) | (64ULL<<32) | (1ULL<<16))
__device__ __forceinline__ uint64_t mk_desc(uint32_t a) {
    return DESC_BASE | (uint64_t)((a >> 4) & 0x3FFF);
}
// F32 acc, BF16 a/b, N=256, M=128
#define IDESC (0x10u | 0x80u | 0x400u | (32u<<17) | (8u<<24))

// ---------------- tcgen05 conv: single 648-row window, kw/kh via desc rows ---
// Item = (n, rg): 8 out rows = 2 tiles of 256 pixels. Window W[j] = X[Q0-65+j],
// j in [0,648). Stage (t,kh,kw): B desc start row r0 = 256t + 64kh + kw
// (rows are LINEAR at 128B each in our layout -> desc offset r0*8 units).
// D = tmem + 256t, all cols real. B staged ONCE per item.
#define SM_TPTR 0
#define SM_MBAR 16
#define SM_A0   1024
#define SM_A1   33792
#define SM_B    66560
#define BROWS   648
#define NARB    81                   // ci-half stride = NARB*1024 B
#define CONV_SMEM (SM_B + BROWS*256) // 232,448 (= 227KB opt-in max)
#define MB_S(s)    (SM_MBAR + (s)*8)
#define EPI_PITCH 68

__global__ __launch_bounds__(128, 1)
void conv_mma_kernel(float* __restrict__ out) {
#if HAS_TCGEN5
    extern __shared__ char smem[];
    const int tid = threadIdx.x;
    const int wid = tid >> 5, lane = tid & 31;
    const uint32_t sb = smem_u32(smem);

    auto stageA = [&](int s) {
        const int kh = s % 3, kw = s / 3;
        const char* gA = (const char*)(g_wq9 + (size_t)(kh * 3 + kw) * COUT * CIN);
        uint32_t abuf = sb + ((s & 1) ? SM_A1 : SM_A0);
        #pragma unroll
        for (int it = 0; it < 16; it++) {
            int i = tid + it * 128;
            int lr = i >> 4, c = i & 15;
            uint32_t byte = (uint32_t)((lr >> 3) + (c >> 3) * 16) * 1024u
                          + (uint32_t)(lr & 7) * 128u + (uint32_t)(c & 7) * 16u;
            byte ^= (byte >> 3) & 0x70u;
            cp16(abuf + byte, gA + ((size_t)lr << 8) + (c << 4));
        }
    };
    auto stageB = [&](long long P0) {
        const char* gB = (const char*)(g_x1 + GUARD_E) + P0 * (CIN * 2);
        #pragma unroll 3
        for (int it = 0; it < 81; it++) {
            int i = tid + it * 128;
            int lr = i >> 4, c16 = i & 15;
            uint32_t byte = (uint32_t)((lr >> 3) + (c16 >> 3) * NARB) * 1024u
                          + (uint32_t)(lr & 7) * 128u + (uint32_t)(c16 & 7) * 16u;
            byte ^= (byte >> 3) & 0x70u;
            cp16(sb + SM_B + byte, gB + ((size_t)lr << 8) + (c16 << 4));
        }
    };

    if (wid == 0) TC_ALLOC(sb + SM_TPTR, 512);
    if (tid == 0)
        for (int m = 0; m < 9; m++) MBAR_INIT(SM_MBAR + sb + m * 8, 1);
    __syncthreads();
    uint32_t tmem;
    asm volatile("ld.shared.b32 %0, [%1];" : "=r"(tmem) : "r"(sb + SM_TPTR));
    if (wid == 0) TC_RELINQ();

    const uint64_t adesc[2] = { mk_desc(sb + SM_A0), mk_desc(sb + SM_A1) };
    const uint64_t bdesc = mk_desc(sb + SM_B);

    for (int rep = 0, item = blockIdx.x; item < NITEMS; rep++, item += NCTAS) {
        const uint32_t par = (uint32_t)(rep & 1);
        const int n = item / 7, h0 = (item % 7) * 8;
        const long long Q0 = ((long long)n * 58 + h0 + 1) * 64;

        stageB(Q0 - 65);
        stageA(0);
        CP_COMMIT(); CP_WAIT0(); FENCE_ASYNC();
        __syncthreads();

        for (int s = 0; s < 9; s++) {
            const int kh = s % 3, kw = s / 3;
            if (tid < 32 && elect_one_pred()) {
                const uint64_t ad = adesc[s & 1];
                #pragma unroll
                for (int t = 0; t < 2; t++) {
                    // row start r0 = 256t + 64kh + kw, linear rows @128B = 8 units/row
                    const uint64_t bd = bdesc + (uint64_t)((256 * t + 64 * kh + kw) * 8);
                    #pragma unroll
                    for (int k = 0; k < 8; k++)
                        mma_f16_ss(tmem + t * 256,
                                   ad + (uint64_t)((k & 3) * 2 + (k >> 2) * 1024),
                                   bd + (uint64_t)((k & 3) * 2 + (k >> 2) * 5184),
                                   IDESC, (s > 0 || k > 0) ? 1u : 0u);
                }
                TC_COMMIT(sb + MB_S(s));
            }
            if (s == 8) break;
            if (s >= 1) mbar_wait(sb + MB_S(s - 1), par);
            stageA(s + 1);
            CP_COMMIT(); CP_WAIT0(); FENCE_ASYNC();
            __syncthreads();
        }

        mbar_wait(sb + MB_S(8), par);
        TC_FENCE_AFTER();
        __syncthreads();          // B smem dead: reuse for epilogue

        // ---- epilogue: tile t, row r: D cols [256t+64r, +63] -> out row h0+4t+r
        float* sepi = reinterpret_cast<float*>(smem + SM_B);
        float* ob = out + (size_t)n * COUT * (HH * WW);
        const int co = wid * 32 + lane;
        #pragma unroll
        for (int t = 0; t < 2; t++) {
            #pragma unroll
            for (int r = 0; r < 4; r++) {
                uint32_t v0[32], v1[32];
                TC_LD_X32(v0, tmem + t * 256 + r * 64);
                TC_LD_X32(v1, tmem + t * 256 + r * 64 + 32);
                TC_WAIT_LD();
                float* myrow = sepi + co * EPI_PITCH;
                #pragma unroll
                for (int j = 0; j < 32; j += 4)
                    *reinterpret_cast<float4*>(myrow + j) =
                        make_float4(__uint_as_float(v0[j]),   __uint_as_float(v0[j+1]),
                                    __uint_as_float(v0[j+2]), __uint_as_float(v0[j+3]));
                #pragma unroll
                for (int j = 0; j < 24; j += 4)   // cols 32..55 only
                    *reinterpret_cast<float4*>(myrow + 32 + j) =
                        make_float4(__uint_as_float(v1[j]),   __uint_as_float(v1[j+1]),
                                    __uint_as_float(v1[j+2]), __uint_as_float(v1[j+3]));
                __syncthreads();
                #pragma unroll
                for (int kq = 0; kq < 14; kq++) {
                    int idx = kq * 128 + tid;
                    int co2 = idx / 14, q = idx % 14;
                    int w = q * 4;
                    float4 val = *reinterpret_cast<float4*>(sepi + co2 * EPI_PITCH + w);
                    stcs128(ob + (size_t)co2 * (HH * WW) + (h0 + 4 * t + r) * WW + w, val);
                }
                __syncthreads();
            }
        }
    }
    if (wid == 0) TC_DEALLOC(tmem, 512);
#endif // HAS_TCGEN5
}

// ---------------- launch ----------------
extern "C" void kernel_launch(void* const* d_in, const int* in_sizes, int n_in,
                              void* d_out, int out_size) {
    const float* x = (const float*)d_in[0];
    const float* w = (const float*)d_in[1];
    if (in_sizes[0] == WN && in_sizes[1] == XN) {
        x = (const float*)d_in[1];
        w = (const float*)d_in[0];
    }
    float* out = (float*)d_out;

    cudaFuncSetAttribute(conv_mma_kernel,
                         cudaFuncAttributeMaxDynamicSharedMemorySize, CONV_SMEM);

    quant_pad_x<<<dim3(7, 8, NB + 1), 256>>>(x, w);
    conv_mma_kernel<<<NCTAS, 128, CONV_SMEM>>>(out);
}

// round 17
// speedup vs baseline: 1.0755x; 1.0056x over previous
#include <cuda_runtime.h>
#include <cuda_bf16.h>
#include <cstdint>

#if defined(__CUDA_ARCH_FEAT_SM103_ALL) || defined(__CUDA_ARCH_FEAT_SM100_ALL) || \
    (defined(__CUDA_ARCH_SPECIFIC__) && (__CUDA_ARCH_SPECIFIC__ >= 1000))
#define HAS_TCGEN5 1
#else
#define HAS_TCGEN5 0
#endif

// ---------------- problem constants ----------------
#define NB   64
#define CIN  128
#define COUT 128
#define HH   56
#define WW   56
#define XN   (NB*CIN*HH*WW)
#define WN   (COUT*CIN*9)
#define WGROUPS (WN/16)            // 576

#define NPIXR   3712               // 58*64 padded pixel rows per image
#define GUARDR  64
#define GUARD_E (GUARDR*CIN)
#define NITEMS  448                // 64 images x 7 groups of 8 out rows
#define NCTAS   448                // 1 item/CTA; 152-SM GB300 -> 3 waves

// ---------------- device scratch ----------------
__device__ __align__(256) __nv_bfloat16 g_x1[(size_t)(2*GUARDR + NB*NPIXR)*CIN];
__device__ __nv_bfloat16 g_wq9[9*COUT*CIN];   // [k=kh*3+kw][co][ci]

// ---------------- BFP quantization (exact, bf16-representable) ----------------
__device__ __forceinline__ void quant16(const float4* p, float* ov) {
    float v[16];
    float4 a = p[0], b = p[1], c = p[2], d = p[3];
    v[0]=a.x;v[1]=a.y;v[2]=a.z;v[3]=a.w; v[4]=b.x;v[5]=b.y;v[6]=b.z;v[7]=b.w;
    v[8]=c.x;v[9]=c.y;v[10]=c.z;v[11]=c.w; v[12]=d.x;v[13]=d.y;v[14]=d.z;v[15]=d.w;
    float m = 0.0f;
    #pragma unroll
    for (int i = 0; i < 16; i++) m = fmaxf(m, fabsf(v[i]));
    if (m > 0.0f) {
        int e = ((__float_as_int(m) >> 23) & 0xFF) - 127;
        float inv_s = ldexpf(1.0f, 7 - e);
        float s     = ldexpf(1.0f, e - 7);
        #pragma unroll
        for (int i = 0; i < 16; i++) {
            float q = rintf(v[i] * inv_s);
            q = fminf(127.0f, fmaxf(-127.0f, q));
            ov[i] = q * s;
        }
    } else {
        #pragma unroll
        for (int i = 0; i < 16; i++) ov[i] = 0.0f;
    }
}

// ---------------- fused prepass: quant x (+transpose/pad) AND quant w --------
__global__ __launch_bounds__(256)
void quant_pad_x(const float* __restrict__ in, const float* __restrict__ win) {
    const int hc = blockIdx.x, cc = blockIdx.y, nz = blockIdx.z;
    const int tid = threadIdx.x;

    if (nz == NB) {   // ---- weight path ----
        int g = (hc * 8 + cc) * 256 + tid;
        if (g < WGROUPS) {
            float ov[16];
            quant16(reinterpret_cast<const float4*>(win) + (size_t)g * 4, ov);
            #pragma unroll
            for (int i = 0; i < 16; i++) {
                int flat = g * 16 + i;
                int k  = flat % 9;
                int t2 = flat / 9;
                int ci = t2 % CIN;
                int co = t2 / CIN;
                g_wq9[(k * COUT + co) * CIN + ci] = __float2bfloat16(ov[i]);
            }
        }
        return;
    }

    __shared__ uint32_t sq[16][229];
    const int n = nz;
    const int h0 = hc * 8, ci0 = cc * 16;

    for (int g2 = tid; g2 < 448; g2 += 256) {
        int ci = g2 / 28, grp = g2 % 28;
        const float4* src = reinterpret_cast<const float4*>(
            in + ((size_t)(n * CIN + ci0 + ci) * (HH * WW) + h0 * WW + grp * 16));
        float ov[16];
        quant16(src, ov);
        int wb = grp * 8;
        #pragma unroll
        for (int j = 0; j < 8; j++) {
            uint32_t lo = __bfloat16_as_ushort(__float2bfloat16(ov[2*j]));
            uint32_t hi = __bfloat16_as_ushort(__float2bfloat16(ov[2*j+1]));
            sq[ci][wb + j] = (hi << 16) | lo;
        }
    }
    __syncthreads();

    __nv_bfloat16* img = g_x1 + GUARD_E + (size_t)n * NPIXR * CIN;
    const uint4 z4 = make_uint4(0, 0, 0, 0);

    for (int i = tid; i < 896; i += 256) {
        int pos = i >> 1, half = i & 1;
        int r = pos / WW, w = pos % WW;
        int p56 = r * WW + w;
        int word = p56 >> 1;
        uint32_t sel = (p56 & 1) ? 0x7632u : 0x5410u;
        const int h8 = half * 8;
        uint4 v;
        v.x = __byte_perm(sq[h8+0][word], sq[h8+1][word], sel);
        v.y = __byte_perm(sq[h8+2][word], sq[h8+3][word], sel);
        v.z = __byte_perm(sq[h8+4][word], sq[h8+5][word], sel);
        v.w = __byte_perm(sq[h8+6][word], sq[h8+7][word], sel);
        int pix = (h0 + r + 1) * 64 + w;
        *reinterpret_cast<uint4*>(img + (size_t)pix * CIN + ci0 + half * 8) = v;
    }
    for (int i = tid; i < 128; i += 256) {
        int r = i >> 4, w2 = (i >> 1) & 7, half = i & 1;
        int pix = (h0 + r + 1) * 64 + 56 + w2;
        *reinterpret_cast<uint4*>(img + (size_t)pix * CIN + ci0 + half * 8) = z4;
    }
    if (hc == 0)
        for (int i = tid; i < 128; i += 256) {
            int pix = i >> 1, half = i & 1;
            *reinterpret_cast<uint4*>(img + (size_t)pix * CIN + ci0 + half * 8) = z4;
        }
    if (hc == 6)
        for (int i = tid; i < 128; i += 256) {
            int pix = 57 * 64 + (i >> 1), half = i & 1;
            *reinterpret_cast<uint4*>(img + (size_t)pix * CIN + ci0 + half * 8) = z4;
        }
    if (n == 0 && hc == 0 && cc == 0)
        for (int i = tid; i < GUARD_E / 8; i += 256)
            reinterpret_cast<uint4*>(g_x1)[i] = z4;
    if (n == NB-1 && hc == 6 && cc == 0) {
        uint4* back = reinterpret_cast<uint4*>(g_x1 + GUARD_E + (size_t)NB * NPIXR * CIN);
        for (int i = tid; i < GUARD_E / 8; i += 256) back[i] = z4;
    }
}

// ---------------- tcgen05 helpers ----------------
#if HAS_TCGEN5
__device__ __forceinline__ uint32_t elect_one_pred() {
    uint32_t pred;
    asm volatile("{\n\t.reg .pred p;\n\telect.sync _|p, 0xFFFFFFFF;\n\t"
                 "selp.b32 %0, 1, 0, p;\n\t}" : "=r"(pred));
    return pred;
}
#define TC_ALLOC(sm, n)  asm volatile("tcgen05.alloc.cta_group::1.sync.aligned.shared::cta.b32 [%0], %1;" :: "r"(sm), "r"((uint32_t)(n)) : "memory")
#define TC_DEALLOC(t, n) asm volatile("tcgen05.dealloc.cta_group::1.sync.aligned.b32 %0, %1;" :: "r"(t), "r"((uint32_t)(n)))
#define TC_RELINQ()      asm volatile("tcgen05.relinquish_alloc_permit.cta_group::1.sync.aligned;")
#define TC_COMMIT(mb)    asm volatile("tcgen05.commit.cta_group::1.mbarrier::arrive::one.shared::cluster.b64 [%0];" :: "r"(mb) : "memory")
#define TC_FENCE_AFTER() asm volatile("tcgen05.fence::after_thread_sync;" ::: "memory")
#define TC_WAIT_LD()     asm volatile("tcgen05.wait::ld.sync.aligned;" ::: "memory")
#define FENCE_ASYNC()    asm volatile("fence.proxy.async.shared::cta;" ::: "memory")
#define MBAR_INIT(mb, c) asm volatile("mbarrier.init.shared.b64 [%0], %1;" :: "r"(mb), "r"((uint32_t)(c)) : "memory")
#define CP_COMMIT()      asm volatile("cp.async.commit_group;" ::: "memory")
#define CP_WAIT0()       asm volatile("cp.async.wait_group 0;" ::: "memory")

__device__ __forceinline__ void cp16(uint32_t dst, const void* src) {
    asm volatile("cp.async.cg.shared.global [%0], [%1], 16;"
                 :: "r"(dst), "l"(src) : "memory");
}
__device__ __forceinline__ void mbar_wait(uint32_t mb, uint32_t parity) {
    asm volatile(
        "{\n\t.reg .pred P1;\n\t"
        "WL_%=:\n\t"
        "mbarrier.try_wait.parity.acquire.cta.shared::cta.b64 P1, [%0], %1, 0x989680;\n\t"
        "@P1 bra.uni WD_%=;\n\t"
        "bra.uni WL_%=;\n\t"
        "WD_%=:\n\t}"
        :: "r"(mb), "r"(parity) : "memory");
}
#define TC_LD_X32(r, ta) \
    asm volatile("tcgen05.ld.sync.aligned.32x32b.x32.b32 " \
        "{%0,%1,%2,%3,%4,%5,%6,%7,%8,%9,%10,%11,%12,%13,%14,%15," \
        "%16,%17,%18,%19,%20,%21,%22,%23,%24,%25,%26,%27,%28,%29,%30,%31}, [%32];" \
        : "=r"((r)[0]),"=r"((r)[1]),"=r"((r)[2]),"=r"((r)[3]),"=r"((r)[4]),"=r"((r)[5]),"=r"((r)[6]),"=r"((r)[7]), \
          "=r"((r)[8]),"=r"((r)[9]),"=r"((r)[10]),"=r"((r)[11]),"=r"((r)[12]),"=r"((r)[13]),"=r"((r)[14]),"=r"((r)[15]), \
          "=r"((r)[16]),"=r"((r)[17]),"=r"((r)[18]),"=r"((r)[19]),"=r"((r)[20]),"=r"((r)[21]),"=r"((r)[22]),"=r"((r)[23]), \
          "=r"((r)[24]),"=r"((r)[25]),"=r"((r)[26]),"=r"((r)[27]),"=r"((r)[28]),"=r"((r)[29]),"=r"((r)[30]),"=r"((r)[31]) \
        : "r"(ta))

__device__ __forceinline__ void mma_f16_ss(uint32_t d, uint64_t a, uint64_t b,
                                           uint32_t idesc, uint32_t en) {
    asm volatile(
        "{\n\t.reg .pred p;\n\tsetp.ne.u32 p, %4, 0;\n\t"
        "tcgen05.mma.cta_group::1.kind::f16 [%0], %1, %2, %3, {%5,%5,%5,%5}, p;\n\t}"
        :: "r"(d), "l"(a), "l"(b), "r"(idesc), "r"(en), "r"(0u) : "memory");
}
#endif // HAS_TCGEN5

__device__ __forceinline__ uint32_t smem_u32(const void* p) {
    uint32_t a;
    asm("{ .reg .u64 t; cvta.to.shared.u64 t, %1; cvt.u32.u64 %0, t; }" : "=r"(a) : "l"(p));
    return a;
}
__device__ __forceinline__ void stcs128(float* p, float4 v) {
    asm volatile("st.global.cs.v4.f32 [%0], {%1,%2,%3,%4};"
                 :: "l"(p), "f"(v.x), "f"(v.y), "f"(v.z), "f"(v.w) : "memory");
}
#define DESC_BASE ((2ULL<<61) | (1ULL<<46) | (64ULL<<32) | (1ULL<<16))
__device__ __forceinline__ uint64_t mk_desc(uint32_t a) {
    return DESC_BASE | (uint64_t)((a >> 4) & 0x3FFF);
}
// F32 acc, BF16 a/b, N=256, M=128
#define IDESC (0x10u | 0x80u | 0x400u | (32u<<17) | (8u<<24))

// ---------------- tcgen05 conv: single 648-row window, kw/kh via desc rows ---
#define SM_TPTR 0
#define SM_MBAR 16
#define SM_A0   1024
#define SM_A1   33792
#define SM_B    66560
#define BROWS   648
#define NARB    81                   // ci-half stride = NARB*1024 B
#define CONV_SMEM (SM_B + BROWS*256) // 232,448
#define MB_S(s)    (SM_MBAR + (s)*8)
#define EPI_PITCH 68

__global__ __launch_bounds__(128, 1)
void conv_mma_kernel(float* __restrict__ out) {
#if HAS_TCGEN5
    extern __shared__ char smem[];
    const int tid = threadIdx.x;
    const int wid = tid >> 5, lane = tid & 31;
    const uint32_t sb = smem_u32(smem);

    auto stageA = [&](int s) {
        const int kh = s % 3, kw = s / 3;
        const char* gA = (const char*)(g_wq9 + (size_t)(kh * 3 + kw) * COUT * CIN);
        uint32_t abuf = sb + ((s & 1) ? SM_A1 : SM_A0);
        #pragma unroll
        for (int it = 0; it < 16; it++) {
            int i = tid + it * 128;
            int lr = i >> 4, c = i & 15;
            uint32_t byte = (uint32_t)((lr >> 3) + (c >> 3) * 16) * 1024u
                          + (uint32_t)(lr & 7) * 128u + (uint32_t)(c & 7) * 16u;
            byte ^= (byte >> 3) & 0x70u;
            cp16(abuf + byte, gA + ((size_t)lr << 8) + (c << 4));
        }
    };
    auto stageB = [&](long long P0) {
        const char* gB = (const char*)(g_x1 + GUARD_E) + P0 * (CIN * 2);
        #pragma unroll 3
        for (int it = 0; it < 81; it++) {
            int i = tid + it * 128;
            int lr = i >> 4, c16 = i & 15;
            uint32_t byte = (uint32_t)((lr >> 3) + (c16 >> 3) * NARB) * 1024u
                          + (uint32_t)(lr & 7) * 128u + (uint32_t)(c16 & 7) * 16u;
            byte ^= (byte >> 3) & 0x70u;
            cp16(sb + SM_B + byte, gB + ((size_t)lr << 8) + (c16 << 4));
        }
    };

    if (wid == 0) TC_ALLOC(sb + SM_TPTR, 512);
    if (tid == 0)
        for (int m = 0; m < 9; m++) MBAR_INIT(SM_MBAR + sb + m * 8, 1);
    __syncthreads();
    uint32_t tmem;
    asm volatile("ld.shared.b32 %0, [%1];" : "=r"(tmem) : "r"(sb + SM_TPTR));
    if (wid == 0) TC_RELINQ();

    const uint64_t adesc[2] = { mk_desc(sb + SM_A0), mk_desc(sb + SM_A1) };
    const uint64_t bdesc = mk_desc(sb + SM_B);

    for (int rep = 0, item = blockIdx.x; item < NITEMS; rep++, item += NCTAS) {
        const uint32_t par = (uint32_t)(rep & 1);
        const int n = item / 7, h0 = (item % 7) * 8;
        const long long Q0 = ((long long)n * 58 + h0 + 1) * 64;

        stageB(Q0 - 65);
        stageA(0);
        CP_COMMIT(); CP_WAIT0(); FENCE_ASYNC();
        __syncthreads();

        for (int s = 0; s < 9; s++) {
            const int kh = s % 3, kw = s / 3;
            if (tid < 32 && elect_one_pred()) {
                const uint64_t ad = adesc[s & 1];
                #pragma unroll
                for (int t = 0; t < 2; t++) {
                    const uint64_t bd = bdesc + (uint64_t)((256 * t + 64 * kh + kw) * 8);
                    #pragma unroll
                    for (int k = 0; k < 8; k++)
                        mma_f16_ss(tmem + t * 256,
                                   ad + (uint64_t)((k & 3) * 2 + (k >> 2) * 1024),
                                   bd + (uint64_t)((k & 3) * 2 + (k >> 2) * 5184),
                                   IDESC, (s > 0 || k > 0) ? 1u : 0u);
                }
                TC_COMMIT(sb + MB_S(s));
            }
            if (s == 8) break;
            if (s >= 1) mbar_wait(sb + MB_S(s - 1), par);
            stageA(s + 1);
            CP_COMMIT(); CP_WAIT0(); FENCE_ASYNC();
            __syncthreads();
        }

        mbar_wait(sb + MB_S(8), par);
        TC_FENCE_AFTER();
        __syncthreads();          // B smem dead: reuse for epilogue

        float* sepi = reinterpret_cast<float*>(smem + SM_B);
        float* ob = out + (size_t)n * COUT * (HH * WW);
        const int co = wid * 32 + lane;
        #pragma unroll
        for (int t = 0; t < 2; t++) {
            #pragma unroll
            for (int r = 0; r < 4; r++) {
                uint32_t v0[32], v1[32];
                TC_LD_X32(v0, tmem + t * 256 + r * 64);
                TC_LD_X32(v1, tmem + t * 256 + r * 64 + 32);
                TC_WAIT_LD();
                float* myrow = sepi + co * EPI_PITCH;
                #pragma unroll
                for (int j = 0; j < 32; j += 4)
                    *reinterpret_cast<float4*>(myrow + j) =
                        make_float4(__uint_as_float(v0[j]),   __uint_as_float(v0[j+1]),
                                    __uint_as_float(v0[j+2]), __uint_as_float(v0[j+3]));
                #pragma unroll
                for (int j = 0; j < 24; j += 4)   // cols 32..55 only
                    *reinterpret_cast<float4*>(myrow + 32 + j) =
                        make_float4(__uint_as_float(v1[j]),   __uint_as_float(v1[j+1]),
                                    __uint_as_float(v1[j+2]), __uint_as_float(v1[j+3]));
                __syncthreads();
                #pragma unroll
                for (int kq = 0; kq < 14; kq++) {
                    int idx = kq * 128 + tid;
                    int co2 = idx / 14, q = idx % 14;
                    int w = q * 4;
                    float4 val = *reinterpret_cast<float4*>(sepi + co2 * EPI_PITCH + w);
                    stcs128(ob + (size_t)co2 * (HH * WW) + (h0 + 4 * t + r) * WW + w, val);
                }
                __syncthreads();
            }
        }
    }
    if (wid == 0) TC_DEALLOC(tmem, 512);
#endif // HAS_TCGEN5
}

// ---------------- launch ----------------
extern "C" void kernel_launch(void* const* d_in, const int* in_sizes, int n_in,
                              void* d_out, int out_size) {
    const float* x = (const float*)d_in[0];
    const float* w = (const float*)d_in[1];
    if (in_sizes[0] == WN && in_sizes[1] == XN) {
        x = (const float*)d_in[1];
        w = (const float*)d_in[0];
    }
    float* out = (float*)d_out;

    cudaFuncSetAttribute(conv_mma_kernel,
                         cudaFuncAttributeMaxDynamicSharedMemorySize, CONV_SMEM);

    quant_pad_x<<<dim3(7, 8, NB + 1), 256>>>(x, w);
    conv_mma_kernel<<<NCTAS, 128, CONV_SMEM>>>(out);
}